// round 16
// baseline (speedup 1.0000x reference)
#include <cuda_runtime.h>
#include <cuda_fp16.h>
#include <cstdint>

// ---------------- problem constants ----------------
#define B_   64
#define V_   2048
#define K_   128
#define H_   128
#define N_   (B_*V_)
#define E_   1048576
#define CF_  47
#define L_   3
#define EPSF 1e-5f
#define SPLITV 4

// ---------------- scratch ----------------
__device__ __half g_Y1h[(size_t)E_*H_];
__device__ __half g_Y2h[(size_t)E_*2*H_];
__device__ float g_H  [(size_t)N_*H_];
__device__ float g_HSp[(size_t)SPLITV*B_*K_*H_];
__device__ __half g_Yah[(size_t)N_*H_];
__device__ __half g_Ybh[(size_t)N_*H_];
__device__ float g_Yo [(size_t)N_*H_];
// 9 BN stat slots: 0=bn1,1=bn2, 2+2l=bnA(l), 3+2l=bnB(l), 8=bno
__device__ float g_sumA[9*256], g_sumsqA[9*256];
// fp16 operands
__device__ __half w1s_hi[64*128];
__device__ __half w2s_hi[128*256];
__device__ __half pw1s_hi[3*256*128];
__device__ __half pw2s_hi[3*128*128];
__device__ __half wo1s_hi[128*128];
__device__ __half g_evhi[(size_t)B_*V_*K_];
__device__ __half g_eihi[(size_t)B_*V_*K_];
__device__ __half g_hhi [(size_t)N_*H_];
__device__ __half g_Thi [(size_t)B_*K_*H_];

// ---------------- helpers ----------------
__device__ __forceinline__ float siluf(float x){ return x * (1.f/(1.f+__expf(-x))); }
__device__ __forceinline__ float softplusf(float x){ return x > 20.f ? x : log1pf(__expf(x)); }
__device__ __forceinline__ void red_add_v4(float* a, float x, float y, float z, float w){
    asm volatile("red.global.add.v4.f32 [%0], {%1,%2,%3,%4};"
                 :: "l"(a), "f"(x), "f"(y), "f"(z), "f"(w) : "memory");
}
__device__ __forceinline__ uint32_t smem_u32(const void* p){
    uint32_t a;
    asm("{ .reg .u64 t; cvta.to.shared.u64 t, %1; cvt.u32.u64 %0, t; }" : "=r"(a) : "l"(p));
    return a;
}
__device__ __forceinline__ void cpasync16(uint32_t s, const void* g){
    asm volatile("cp.async.ca.shared.global [%0], [%1], 16;" :: "r"(s), "l"(g));
}
#define CP_COMMIT() asm volatile("cp.async.commit_group;")
#define CP_WAIT0()  asm volatile("cp.async.wait_group 0;")

__device__ __forceinline__ void ldsm4(uint32_t* r, uint32_t addr){
    asm volatile("ldmatrix.sync.aligned.m8n8.x4.shared.b16 {%0,%1,%2,%3}, [%4];"
        : "=r"(r[0]),"=r"(r[1]),"=r"(r[2]),"=r"(r[3]) : "r"(addr));
}
__device__ __forceinline__ void ldsm4t(uint32_t* r, uint32_t addr){
    asm volatile("ldmatrix.sync.aligned.m8n8.x4.trans.shared.b16 {%0,%1,%2,%3}, [%4];"
        : "=r"(r[0]),"=r"(r[1]),"=r"(r[2]),"=r"(r[3]) : "r"(addr));
}
__device__ __forceinline__ void mma16816(float* d, const uint32_t* a, uint32_t b0, uint32_t b1){
    asm volatile("mma.sync.aligned.m16n8k16.row.col.f32.f16.f16.f32 "
        "{%0,%1,%2,%3}, {%4,%5,%6,%7}, {%8,%9}, {%0,%1,%2,%3};"
        : "+f"(d[0]),"+f"(d[1]),"+f"(d[2]),"+f"(d[3])
        : "r"(a[0]),"r"(a[1]),"r"(a[2]),"r"(a[3]), "r"(b0),"r"(b1));
}

__device__ __forceinline__ uint4 cvt8h(const float* f){
    unsigned h[4];
    #pragma unroll
    for (int p=0;p<4;p++){
        __half2 hh = __float22half2_rn(make_float2(f[2*p], f[2*p+1]));
        h[p] = *reinterpret_cast<unsigned*>(&hh);
    }
    return make_uint4(h[0],h[1],h[2],h[3]);
}
__device__ __forceinline__ void unpack8h(uint4 u, float* f){
    const unsigned v[4] = {u.x, u.y, u.z, u.w};
    #pragma unroll
    for (int p=0;p<4;p++){
        float2 a = __half22float2(*reinterpret_cast<const __half2*>(&v[p]));
        f[2*p] = a.x; f[2*p+1] = a.y;
    }
}
__device__ __forceinline__ void bn_coef(const float* sum, const float* sumsq,
                                        const float* gam, const float* bet,
                                        float Rinv, int c, float& sc, float& sh){
    const float m   = sum[c]*Rinv;
    const float var = sumsq[c]*Rinv - m*m;
    sc = gam[c] * rsqrtf(var + EPSF);
    sh = bet[c] - m*sc;
}

__global__ void zero_kernel(float* __restrict__ p, size_t n){
    size_t i = (size_t)blockIdx.x*blockDim.x + threadIdx.x;
    if (i < n) p[i] = 0.f;
}
__global__ void init_all(float* __restrict__ outp){
    const int t = threadIdx.x;
    #pragma unroll
    for (int s=0;s<9;s++){ g_sumA[s*256+t]=0.f; g_sumsqA[s*256+t]=0.f; }
    if (t < 64) outp[t] = 0.f;
}

// ---------------- prep: all weights in one kernel ----------------
// layout: [0,8192) w1 padded | [8192,40960) w2 | [40960,139264) pw1
//         [139264,188416) pw2 | [188416,204800) wo1
__global__ void split_all_weights(const float* __restrict__ w1, const float* __restrict__ w2,
                                  const float* __restrict__ pw1, const float* __restrict__ pw2,
                                  const float* __restrict__ wo1){
    const int i = blockIdx.x*256 + threadIdx.x;
    if (i < 8192){
        int k = i >> 7, n = i & 127;
        w1s_hi[i] = __float2half_rn((k < CF_) ? w1[k*128 + n] : 0.f);
        return;
    }
    int j = i - 8192;
    if (j < 32768){ w2s_hi[j] = __float2half_rn(w2[j]); return; }
    j -= 32768;
    if (j < 98304){ pw1s_hi[j] = __float2half_rn(pw1[j]); return; }
    j -= 98304;
    if (j < 49152){ pw2s_hi[j] = __float2half_rn(pw2[j]); return; }
    j -= 49152;
    if (j < 16384) wo1s_hi[j] = __float2half_rn(wo1[j]);
}
__global__ void split_eigs_k(const float* __restrict__ eigs){
    size_t i = (size_t)blockIdx.x*256 + threadIdx.x;
    size_t b = i >> 18, rem = i & 0x3FFFF;
    const float* base = eigs + (b*(size_t)(2*V_+1) + 1)*K_;
    g_evhi[i] = __float2half_rn(base[rem]);
    g_eihi[i] = __float2half_rn(base[(size_t)V_*K_ + rem]);
}

// ================= pipelined HMMA fp16 GEMM =================
// D = Ah*Bh, fp32 accum.
// ASRC 0: A fp32 plain, guarded scalar loads (GEMM1, Kd=47; skips all-zero k16 steps)
// ASRC 2: A fp16 (Afh), silu(A*scale+shift), coefs computed in-block from stats
// ASRC 3: A pre-converted fp16 (cp.async)
// ASRC 5: dual concat: kc<4 -> (h @ Bhi); kc>=4 -> (evecs[batch] @ B2hi[batch])
// ASRC 6: A = sum of SPLITV fp32 partials * exp(-eig[row]*t[col])
#define APITCH 80
#define BPITCH 272
#define SMBUF  18944
template<int ASRC, bool STATS, bool OUTHALF>
__global__ void __launch_bounds__(256,2) gemm5(
    const float* __restrict__ Af, const __half* __restrict__ Afh,
    const __half* __restrict__ Ahi, const __half* __restrict__ A2hi,
    const __half* __restrict__ Bhi, const __half* __restrict__ B2hi,
    const float* __restrict__ bias, float* __restrict__ C,
    __half* __restrict__ Chi,
    int Kd, int Nd, int lda,
    size_t sAs, size_t sBs, size_t sC,
    const float* __restrict__ eigsp, const float* __restrict__ ptp, int lidx,
    const float* __restrict__ bnSum, const float* __restrict__ bnSumsq,
    const float* __restrict__ bnGam, const float* __restrict__ bnBet, float bnRinv,
    float* __restrict__ stSum, float* __restrict__ stSumsq)
{
    extern __shared__ __align__(16) uint8_t smem[];
    const uint32_t sb = smem_u32(smem);
    const int tid = threadIdx.x;
    const int lane = tid & 31, wid = tid >> 5;
    const int warpm = wid & 3, warpn = wid >> 2;
    const int brow = blockIdx.y * 128;
    const int bcol = blockIdx.x * 128;
    const int bz   = blockIdx.z;
    Ahi += sAs*bz; Bhi += sBs*bz;
    if (ASRC == 6) Af += (size_t)K_*H_*bz;
    if (C)   C   += sC*bz;
    if (Chi) Chi += sC*bz;
    const int bb = brow >> 11;
    const size_t a2base = (size_t)bb*V_*K_ + (size_t)(brow & 2047)*K_;
    const size_t b2base = (size_t)bb*K_*H_;

    const int nch = (Kd + 31) >> 5;

    const int ar = tid >> 1, akh = (tid & 1) * 16;
    const int bkr = tid >> 3, bns = (tid & 7) * 16;

    float* bnsc = reinterpret_cast<float*>(smem + 2*SMBUF + 1024);
    float* bnsh = bnsc + 128;
    if (ASRC == 2){
        if (tid < 128){
            float sc, sh;
            bn_coef(bnSum, bnSumsq, bnGam, bnBet, bnRinv, tid, sc, sh);
            bnsc[tid] = sc; bnsh[tid] = sh;
        }
        __syncthreads();
    }

    auto stageB = [&](int kc, int buf){
        const __half* shi; size_t so;
        if (ASRC == 5 && kc >= 4){
            const int gk = (kc & 3)*32 + bkr;
            shi = B2hi + b2base;
            so = (size_t)gk*128 + bns;
        } else {
            const int gk = kc*32 + bkr;
            shi = Bhi;
            so = (size_t)gk*Nd + bcol + bns;
        }
        const uint32_t dst = sb + buf*SMBUF + 10240 + bkr*BPITCH + bns*2;
        cpasync16(dst,      shi + so);
        cpasync16(dst + 16, shi + so + 8);
    };
    auto stageA_async = [&](int kc, int buf){
        const __half* hi; size_t so;
        if (ASRC == 5){
            if (kc < 4){ hi = Ahi; so = (size_t)(brow+ar)*128 + kc*32 + akh; }
            else { hi = A2hi + a2base; so = (size_t)ar*K_ + (kc & 3)*32 + akh; }
        } else {
            hi = Ahi;
            so = (size_t)(brow + ar)*lda + kc*32 + akh;
        }
        const uint32_t dst = sb + buf*SMBUF + ar*APITCH + akh*2;
        cpasync16(dst,      hi + so);
        cpasync16(dst + 16, hi + so + 8);
    };
    auto loadA_f32 = [&](int kc, float* av){
        if (ASRC == 2){
            const __half* S = Afh + (size_t)(brow+ar)*lda + kc*32 + akh;
            unpack8h(*reinterpret_cast<const uint4*>(S),     &av[0]);
            unpack8h(*reinterpret_cast<const uint4*>(S + 8), &av[8]);
        } else if (ASRC == 6){
            const float* S = Af + (size_t)(brow+ar)*lda + kc*32 + akh;
            const size_t P = (size_t)B_*K_*H_;
            #pragma unroll
            for (int q=0;q<4;q++){
                float4 v0 = *reinterpret_cast<const float4*>(S + q*4);
                float4 v1 = *reinterpret_cast<const float4*>(S + P + q*4);
                float4 v2 = *reinterpret_cast<const float4*>(S + 2*P + q*4);
                float4 v3 = *reinterpret_cast<const float4*>(S + 3*P + q*4);
                av[q*4+0] = v0.x + v1.x + v2.x + v3.x;
                av[q*4+1] = v0.y + v1.y + v2.y + v3.y;
                av[q*4+2] = v0.z + v1.z + v2.z + v3.z;
                av[q*4+3] = v0.w + v1.w + v2.w + v3.w;
            }
        } else {
            #pragma unroll
            for (int j=0;j<16;j++){
                const int k = kc*32 + akh + j;
                av[j] = (k < Kd) ? Af[(size_t)(brow+ar)*lda + k] : 0.f;
            }
        }
    };
    auto storeA_f32 = [&](int kc, int buf, float* av){
        if (ASRC == 2){
            #pragma unroll
            for (int j=0;j<16;j++){
                const int k = kc*32 + akh + j;
                av[j] = siluf(av[j]*bnsc[k] + bnsh[k]);
            }
        }
        if (ASRC == 6){
            const float eig_a = eigsp[(size_t)bz*(2*V_+1)*K_ + brow + ar];
            #pragma unroll
            for (int j=0;j<16;j++){
                const int k = kc*32 + akh + j;
                av[j] *= __expf(-eig_a * fmaxf(ptp[lidx*H_ + k], 1e-6f));
            }
        }
        uint8_t* base = smem + buf*SMBUF + ar*APITCH + akh*2;
        *reinterpret_cast<uint4*>(base)      = cvt8h(&av[0]);
        *reinterpret_cast<uint4*>(base + 16) = cvt8h(&av[8]);
    };

    constexpr bool A_F32 = (ASRC == 0) || (ASRC == 2) || (ASRC == 6);

    float d[2][8][4];
    #pragma unroll
    for (int i=0;i<2;i++)
        #pragma unroll
        for (int j=0;j<8;j++)
            #pragma unroll
            for (int q=0;q<4;q++) d[i][j][q] = 0.f;

    float av[16];
    stageB(0, 0);
    if (A_F32){ loadA_f32(0, av); storeA_f32(0, 0, av); }
    else       stageA_async(0, 0);
    CP_COMMIT();
    CP_WAIT0();
    __syncthreads();

    for (int kc = 0; kc < nch; kc++){
        const int cur = kc & 1, nxt = cur ^ 1;
        const bool more = (kc + 1 < nch);
        if (more){
            stageB(kc+1, nxt);
            if (!A_F32) stageA_async(kc+1, nxt);
            CP_COMMIT();
            if (A_F32) loadA_f32(kc+1, av);
        }
        const uint32_t aHi = sb + cur*SMBUF;
        const uint32_t bHi = aHi + 10240;
        #pragma unroll
        for (int ks=0; ks<2; ks++){
            if (ASRC != 0 || kc*32 + ks*16 < Kd){
                uint32_t ah[2][4];
                #pragma unroll
                for (int mb=0; mb<2; mb++){
                    const uint32_t ao = (uint32_t)(warpm*32 + mb*16 + (lane & 15))*APITCH
                                      + ks*32 + ((lane >> 4)*16);
                    ldsm4(ah[mb], aHi + ao);
                }
                #pragma unroll
                for (int np=0; np<4; np++){
                    const int n0 = warpn*64 + np*16;
                    const uint32_t bo = (uint32_t)(ks*16 + (lane & 15))*BPITCH
                                      + (uint32_t)n0*2 + ((lane >> 4)*16);
                    uint32_t bh[4];
                    ldsm4t(bh, bHi + bo);
                    #pragma unroll
                    for (int mb=0; mb<2; mb++){
                        mma16816(d[mb][np*2  ], ah[mb], bh[0], bh[1]);
                        mma16816(d[mb][np*2+1], ah[mb], bh[2], bh[3]);
                    }
                }
            }
        }
        if (more){
            if (A_F32) storeA_f32(kc+1, nxt, av);
            CP_WAIT0();
        }
        __syncthreads();
    }

    #pragma unroll
    for (int mb=0; mb<2; mb++){
        #pragma unroll
        for (int nb=0; nb<8; nb++){
            const int m = brow + warpm*32 + mb*16 + (lane >> 2);
            const int n = bcol + warpn*64 + nb*8 + (lane & 3)*2;
            float b0 = 0.f, b1 = 0.f;
            if (bias){ b0 = bias[n]; b1 = bias[n+1]; }
            d[mb][nb][0] += b0; d[mb][nb][1] += b1;
            d[mb][nb][2] += b0; d[mb][nb][3] += b1;
            if (OUTHALF){
                __half2 h2 = __float22half2_rn(make_float2(d[mb][nb][0], d[mb][nb][1]));
                *reinterpret_cast<__half2*>(Chi + (size_t)m*Nd + n) = h2;
                __half2 h3 = __float22half2_rn(make_float2(d[mb][nb][2], d[mb][nb][3]));
                *reinterpret_cast<__half2*>(Chi + (size_t)(m+8)*Nd + n) = h3;
            } else {
                *reinterpret_cast<float2*>(C + (size_t)m*Nd + n) =
                    make_float2(d[mb][nb][0], d[mb][nb][1]);
                *reinterpret_cast<float2*>(C + (size_t)(m+8)*Nd + n) =
                    make_float2(d[mb][nb][2], d[mb][nb][3]);
            }
        }
    }

    if (STATS){
        float* sred = reinterpret_cast<float*>(smem + 2*SMBUF);
        sred[tid] = 0.f;
        __syncthreads();
        float s[16], q[16];
        #pragma unroll
        for (int i=0;i<16;i++){ s[i]=0.f; q[i]=0.f; }
        #pragma unroll
        for (int mb=0; mb<2; mb++)
            #pragma unroll
            for (int nb=0; nb<8; nb++){
                s[nb*2+0] += d[mb][nb][0] + d[mb][nb][2];
                s[nb*2+1] += d[mb][nb][1] + d[mb][nb][3];
                q[nb*2+0] += d[mb][nb][0]*d[mb][nb][0] + d[mb][nb][2]*d[mb][nb][2];
                q[nb*2+1] += d[mb][nb][1]*d[mb][nb][1] + d[mb][nb][3]*d[mb][nb][3];
            }
        #pragma unroll
        for (int off=4; off<32; off<<=1){
            #pragma unroll
            for (int i=0;i<16;i++){
                s[i] += __shfl_xor_sync(0xFFFFFFFFu, s[i], off);
                q[i] += __shfl_xor_sync(0xFFFFFFFFu, q[i], off);
            }
        }
        if (lane < 4){
            #pragma unroll
            for (int i=0;i<16;i++){
                const int col = warpn*64 + (i>>1)*8 + (lane & 3)*2 + (i & 1);
                atomicAdd(&sred[col], s[i]);
                atomicAdd(&sred[128+col], q[i]);
            }
        }
        __syncthreads();
        if (tid < 128){
            atomicAdd(&stSum  [bcol + tid], sred[tid]);
            atomicAdd(&stSumsq[bcol + tid], sred[128 + tid]);
        }
    }
}

// ================= spectral forward =================
#define SSMBUF 17408
__global__ void __launch_bounds__(256,2) spec5(float* __restrict__ HSp)
{
    extern __shared__ __align__(16) uint8_t smem[];
    const uint32_t sb = smem_u32(smem);
    const int b   = blockIdx.z;
    const int seg = blockIdx.x;
    const __half* Ahi = g_eihi + (size_t)b*V_*K_;
    const __half* Bhi = g_hhi  + (size_t)b*V_*H_;

    const int tid = threadIdx.x;
    const int lane = tid & 31, wid = tid >> 5;
    const int warpm = wid & 3, warpn = wid >> 2;
    const int vr = tid >> 3, cs = (tid & 7) * 16;
    const int v0 = seg * (V_/SPLITV);
    const int nch = V_/SPLITV/32;

    auto stage = [&](int vc, int buf){
        const int v = v0 + vc*32 + vr;
        const size_t soA = (size_t)v*K_ + cs;
        const size_t soB = (size_t)v*H_ + cs;
        const uint32_t base = sb + buf*SSMBUF + vr*BPITCH + cs*2;
        cpasync16(base,             Ahi + soA);
        cpasync16(base + 16,        Ahi + soA + 8);
        cpasync16(base + 8704,      Bhi + soB);
        cpasync16(base + 8704 + 16, Bhi + soB + 8);
    };

    float d[2][8][4];
    #pragma unroll
    for (int i=0;i<2;i++)
        #pragma unroll
        for (int j=0;j<8;j++)
            #pragma unroll
            for (int q=0;q<4;q++) d[i][j][q] = 0.f;

    stage(0, 0);
    CP_COMMIT();
    CP_WAIT0();
    __syncthreads();

    for (int vc = 0; vc < nch; vc++){
        const int cur = vc & 1, nxt = cur ^ 1;
        const bool more = (vc + 1 < nch);
        if (more){ stage(vc+1, nxt); CP_COMMIT(); }

        const uint32_t aHi = sb + cur*SSMBUF;
        const uint32_t bHi = aHi + 8704;
        #pragma unroll
        for (int ks=0; ks<2; ks++){
            uint32_t ah[2][4];
            #pragma unroll
            for (int mb=0; mb<2; mb++){
                const uint32_t ao = (uint32_t)(ks*16 + (lane & 7) + ((lane >> 4)*8))*BPITCH
                                  + (uint32_t)(warpm*32 + mb*16)*2 + (((lane >> 3) & 1)*16);
                ldsm4t(ah[mb], aHi + ao);
            }
            #pragma unroll
            for (int np=0; np<4; np++){
                const int n0 = warpn*64 + np*16;
                const uint32_t bo = (uint32_t)(ks*16 + (lane & 15))*BPITCH
                                  + (uint32_t)n0*2 + ((lane >> 4)*16);
                uint32_t bh[4];
                ldsm4t(bh, bHi + bo);
                #pragma unroll
                for (int mb=0; mb<2; mb++){
                    mma16816(d[mb][np*2  ], ah[mb], bh[0], bh[1]);
                    mma16816(d[mb][np*2+1], ah[mb], bh[2], bh[3]);
                }
            }
        }
        if (more) CP_WAIT0();
        __syncthreads();
    }

    float* Cb = HSp + (size_t)seg*B_*K_*H_ + (size_t)b*K_*H_;
    #pragma unroll
    for (int mb=0; mb<2; mb++)
        #pragma unroll
        for (int nb=0; nb<8; nb++){
            const int m = warpm*32 + mb*16 + (lane >> 2);
            const int n = warpn*64 + nb*8 + (lane & 3)*2;
            *reinterpret_cast<float2*>(Cb + (size_t)m*H_ + n) =
                make_float2(d[mb][nb][0], d[mb][nb][1]);
            *reinterpret_cast<float2*>(Cb + (size_t)(m+8)*H_ + n) =
                make_float2(d[mb][nb][2], d[mb][nb][3]);
        }
}

// ---------------- message + scatter-add ----------------
__global__ void msg_scatter(const __half* __restrict__ Y2h, const int* __restrict__ vid,
                            float* __restrict__ Hout,
                            const float* __restrict__ g2, const float* __restrict__ be2,
                            float Rinv)
{
    __shared__ float sc[256], sh[256];
    const int tid = threadIdx.x;
    for (int c = tid; c < 256; c += 128){
        float a, b;
        bn_coef(g_sumA + 1*256, g_sumsqA + 1*256, g2, be2, Rinv, c, a, b);
        sc[c] = a; sh[c] = b;
    }
    __syncthreads();

    const int sub = tid >> 5;
    const int c4  = (tid & 31) * 4;
    const int e0  = blockIdx.x * 32 + sub * 8;
    const float s0=sc[c4], s1=sc[c4+1], s2=sc[c4+2], s3=sc[c4+3];
    const float t0=sh[c4], t1=sh[c4+1], t2=sh[c4+2], t3=sh[c4+3];
    const float u0=sc[128+c4], u1=sc[129+c4], u2=sc[130+c4], u3=sc[131+c4];
    const float w0=sh[128+c4], w1=sh[129+c4], w2=sh[130+c4], w3=sh[131+c4];
    #pragma unroll
    for (int i=0;i<8;i++){
        const int e = e0 + i;
        uint2 fu = *reinterpret_cast<const uint2*>(Y2h + (size_t)e*256 + c4);
        uint2 cu = *reinterpret_cast<const uint2*>(Y2h + (size_t)e*256 + 128 + c4);
        float2 fa = __half22float2(*reinterpret_cast<const __half2*>(&fu.x));
        float2 fb = __half22float2(*reinterpret_cast<const __half2*>(&fu.y));
        float2 ca = __half22float2(*reinterpret_cast<const __half2*>(&cu.x));
        float2 cb = __half22float2(*reinterpret_cast<const __half2*>(&cu.y));
        float m0 = (1.f/(1.f+__expf(-(fa.x*s0+t0)))) * softplusf(ca.x*u0+w0);
        float m1 = (1.f/(1.f+__expf(-(fa.y*s1+t1)))) * softplusf(ca.y*u1+w1);
        float m2 = (1.f/(1.f+__expf(-(fb.x*s2+t2)))) * softplusf(cb.x*u2+w2);
        float m3 = (1.f/(1.f+__expf(-(fb.y*s3+t3)))) * softplusf(cb.y*u3+w3);
        const int v = vid[e];
        red_add_v4(Hout + (size_t)v*128 + c4, m0, m1, m2, m3);
    }
}

// h += bn(Ybh); also emit fp16 H
__global__ void h_update_split(float* __restrict__ H, const __half* __restrict__ Ybh,
                               const float* __restrict__ sum, const float* __restrict__ sumsq,
                               const float* __restrict__ g, const float* __restrict__ be,
                               float Rinv)
{
    __shared__ float sc[128], sh[128];
    const int tid = threadIdx.x;
    if (tid < 128){
        float a, b;
        bn_coef(sum, sumsq, g, be, Rinv, tid, a, b);
        sc[tid] = a; sh[tid] = b;
    }
    __syncthreads();
    const size_t i = (size_t)blockIdx.x*256 + tid;
    const int c = (int)(i & 127);
    const float v = H[i] + __half2float(Ybh[i])*sc[c] + sh[c];
    H[i] = v;
    g_hhi[i] = __float2half_rn(v);
}
__global__ void split_H(const float* __restrict__ H){
    const size_t i = (size_t)blockIdx.x*256 + threadIdx.x;
    g_hhi[i] = __float2half_rn(H[i]);
}

// out[b] += mean_v( silu(bn(Yo)) . wo2 + bo2 )
__global__ void out_reduce(const float* __restrict__ Yo, const float* __restrict__ wo2,
                           const float* __restrict__ bo2, float* __restrict__ out,
                           const float* __restrict__ go, const float* __restrict__ beo,
                           float Rinv)
{
    __shared__ float sc[128], sh[128];
    const int tid = threadIdx.x;
    if (tid < 128){
        float a, b;
        bn_coef(g_sumA + 8*256, g_sumsqA + 8*256, go, beo, Rinv, tid, a, b);
        sc[tid] = a; sh[tid] = b;
    }
    __syncthreads();
    const int warp = tid >> 5, lane = tid & 31;
    const long n = (long)blockIdx.x*8 + warp;
    float s = 0.f;
    #pragma unroll
    for (int j=0;j<4;j++){
        const int h = lane + j*32;
        float x = Yo[(size_t)n*128 + h]*sc[h] + sh[h];
        x = siluf(x);
        s += x * wo2[h];
    }
    #pragma unroll
    for (int o=16;o>0;o>>=1) s += __shfl_xor_sync(0xFFFFFFFFu, s, o);
    if (lane == 0){
        const int b = (int)(n >> 11);
        atomicAdd(&out[b], (s + bo2[0]) * (1.f/(float)V_));
    }
}

// ---------------- launcher ----------------
extern "C" void kernel_launch(void* const* d_in, const int* in_sizes, int n_in,
                              void* d_out, int out_size)
{
    const float* chem = (const float*)d_in[0];
    const int*   vid  = (const int*  )d_in[1];
    const float* eigs = (const float*)d_in[2];
    const float* w1   = (const float*)d_in[3];
    const float* b1   = (const float*)d_in[4];
    const float* g1   = (const float*)d_in[5];
    const float* be1  = (const float*)d_in[6];
    const float* w2   = (const float*)d_in[7];
    const float* b2   = (const float*)d_in[8];
    const float* g2   = (const float*)d_in[9];
    const float* be2  = (const float*)d_in[10];
    const float* ptim = (const float*)d_in[11];
    const float* pw1  = (const float*)d_in[12];
    const float* pb1  = (const float*)d_in[13];
    const float* pg1  = (const float*)d_in[14];
    const float* pbe1 = (const float*)d_in[15];
    const float* pw2  = (const float*)d_in[16];
    const float* pb2  = (const float*)d_in[17];
    const float* pg2  = (const float*)d_in[18];
    const float* pbe2 = (const float*)d_in[19];
    const float* wo1  = (const float*)d_in[20];
    const float* bo1  = (const float*)d_in[21];
    const float* go1  = (const float*)d_in[22];
    const float* beo1 = (const float*)d_in[23];
    const float* wo2  = (const float*)d_in[24];
    const float* bo2  = (const float*)d_in[25];
    float* outp = (float*)d_out;

    void* p;
    float *pH,*pHSp,*pYo,*pSum,*pSumsq;
    __half *pY1h,*pY2h,*pYah,*pYbh;
    __half *pw1hi,*pw2hi,*ppw1hi,*ppw2hi,*pwo1hi;
    __half *pevhi,*phhi,*pThi;
    cudaGetSymbolAddress(&p, g_Y1h); pY1h=(__half*)p;
    cudaGetSymbolAddress(&p, g_Y2h); pY2h=(__half*)p;
    cudaGetSymbolAddress(&p, g_H );  pH  =(float*)p;
    cudaGetSymbolAddress(&p, g_HSp); pHSp=(float*)p;
    cudaGetSymbolAddress(&p, g_Yah); pYah=(__half*)p;
    cudaGetSymbolAddress(&p, g_Ybh); pYbh=(__half*)p;
    cudaGetSymbolAddress(&p, g_Yo);  pYo =(float*)p;
    cudaGetSymbolAddress(&p, g_sumA);   pSum  =(float*)p;
    cudaGetSymbolAddress(&p, g_sumsqA); pSumsq=(float*)p;
    cudaGetSymbolAddress(&p, w1s_hi); pw1hi=(__half*)p;
    cudaGetSymbolAddress(&p, w2s_hi); pw2hi=(__half*)p;
    cudaGetSymbolAddress(&p, pw1s_hi); ppw1hi=(__half*)p;
    cudaGetSymbolAddress(&p, pw2s_hi); ppw2hi=(__half*)p;
    cudaGetSymbolAddress(&p, wo1s_hi); pwo1hi=(__half*)p;
    cudaGetSymbolAddress(&p, g_evhi); pevhi=(__half*)p;
    cudaGetSymbolAddress(&p, g_hhi ); phhi=(__half*)p;
    cudaGetSymbolAddress(&p, g_Thi ); pThi=(__half*)p;

    const int GSM = 2*SMBUF + 2048;   // 39936
    const int SSM = 2*SSMBUF;
    cudaFuncSetAttribute(gemm5<0,true ,true >, cudaFuncAttributeMaxDynamicSharedMemorySize, GSM);
    cudaFuncSetAttribute(gemm5<2,true ,true >, cudaFuncAttributeMaxDynamicSharedMemorySize, GSM);
    cudaFuncSetAttribute(gemm5<6,false,true >, cudaFuncAttributeMaxDynamicSharedMemorySize, GSM);
    cudaFuncSetAttribute(gemm5<5,true ,true >, cudaFuncAttributeMaxDynamicSharedMemorySize, GSM);
    cudaFuncSetAttribute(gemm5<3,true ,false>, cudaFuncAttributeMaxDynamicSharedMemorySize, GSM);
    cudaFuncSetAttribute(spec5, cudaFuncAttributeMaxDynamicSharedMemorySize, SSM);

    const float RinvE = 1.f/(float)E_;
    const float RinvN = 1.f/(float)N_;

    // launch 1: all weights
    split_all_weights<<<(8192+32768+98304+49152+16384)/256, 256>>>(w1, w2, pw1, pw2, wo1);
    // launch 2: stats + out init
    init_all<<<1, 256>>>(outp);
    // launch 3: chem MLP stage 1 -> stats slot 0
    gemm5<0,true,true><<<dim3(1, E_/128, 1), 256, GSM>>>(
        chem, nullptr, nullptr, nullptr, pw1hi, nullptr,
        b1, nullptr, pY1h, CF_, 128, CF_, 0, 0, 0, nullptr, nullptr, 0,
        nullptr, nullptr, nullptr, nullptr, 0.f,
        pSum + 0*256, pSumsq + 0*256);
    // launch 4 (profiled): stage 2 -> slot 1
    gemm5<2,true,true><<<dim3(2, E_/128, 1), 256, GSM>>>(
        nullptr, pY1h, nullptr, nullptr, pw2hi, nullptr,
        b2, nullptr, pY2h, 128, 256, 128, 0, 0, 0, nullptr, nullptr, 0,
        pSum + 0*256, pSumsq + 0*256, g1, be1, RinvE,
        pSum + 1*256, pSumsq + 1*256);

    // remaining prep (needed only by spec/zMLP1)
    split_eigs_k<<<(unsigned)(((size_t)B_*V_*K_)/256), 256>>>(eigs);

    // ---- message + segment_sum (consume slot 1) ----
    zero_kernel<<<(unsigned)(((size_t)N_*H_)/256), 256>>>(pH, (size_t)N_*H_);
    msg_scatter<<<E_/32, 128>>>(pY2h, vid, pH, g2, be2, RinvE);
    split_H<<<(unsigned)(((size_t)N_*H_)/256), 256>>>(pH);

    // ---- propagation layers ----
    for (int l = 0; l < L_; l++){
        spec5<<<dim3(SPLITV, 1, B_), 256, SSM>>>(pHSp);
        gemm5<6,false,true><<<dim3(1, 1, B_), 256, GSM>>>(
            pHSp, nullptr, nullptr, nullptr,
            ppw1hi + (size_t)l*256*128 + 128*128, nullptr,
            nullptr, nullptr, pThi,
            128, 128, 128, 0, 0, (size_t)K_*H_, eigs, ptim, l,
            nullptr, nullptr, nullptr, nullptr, 0.f, nullptr, nullptr);
        gemm5<5,true,true><<<dim3(1, N_/128, 1), 256, GSM>>>(
            nullptr, nullptr, phhi, pevhi,
            ppw1hi + (size_t)l*256*128, pThi,
            pb1 + l*H_, nullptr, pYah, 256, 128, 128, 0, 0, 0, nullptr, nullptr, 0,
            nullptr, nullptr, nullptr, nullptr, 0.f,
            pSum + (2+2*l)*256, pSumsq + (2+2*l)*256);
        gemm5<2,true,true><<<dim3(1, N_/128, 1), 256, GSM>>>(
            nullptr, pYah, nullptr, nullptr,
            ppw2hi + (size_t)l*128*128, nullptr,
            pb2 + l*H_, nullptr, pYbh, 128, 128, 128, 0, 0, 0, nullptr, nullptr, 0,
            pSum + (2+2*l)*256, pSumsq + (2+2*l)*256, pg1 + l*H_, pbe1 + l*H_, RinvN,
            pSum + (3+2*l)*256, pSumsq + (3+2*l)*256);
        h_update_split<<<(unsigned)(((size_t)N_*H_)/256), 256>>>(
            pH, pYbh, pSum + (3+2*l)*256, pSumsq + (3+2*l)*256,
            pg2 + l*H_, pbe2 + l*H_, RinvN);
    }

    // ---- output head -> stats slot 8 ----
    gemm5<3,true,false><<<dim3(1, N_/128, 1), 256, GSM>>>(
        nullptr, nullptr, phhi, nullptr, pwo1hi, nullptr,
        bo1, pYo, nullptr, 128, 128, 128, 0, 0, 0, nullptr, nullptr, 0,
        nullptr, nullptr, nullptr, nullptr, 0.f,
        pSum + 8*256, pSumsq + 8*256);
    out_reduce<<<N_/8, 256>>>(pYo, wo2, bo2, outp, go1, beo1, RinvN);
}

// round 17
// speedup vs baseline: 1.0648x; 1.0648x over previous
#include <cuda_runtime.h>
#include <cuda_fp16.h>
#include <cstdint>

// ---------------- problem constants ----------------
#define B_   64
#define V_   2048
#define K_   128
#define H_   128
#define N_   (B_*V_)
#define E_   1048576
#define CF_  47
#define L_   3
#define EPSF 1e-5f
#define SPLITV 4

// ---------------- scratch ----------------
__device__ __half g_Y1h[(size_t)E_*H_];
__device__ __half g_Xh [(size_t)E_*H_];      // silu(bn(Y1)) fp16
__device__ __half g_Y2h[(size_t)E_*2*H_];
__device__ float g_H  [(size_t)N_*H_];
__device__ float g_HSp[(size_t)SPLITV*B_*K_*H_];
__device__ __half g_Yah[(size_t)N_*H_];
__device__ __half g_Ybh[(size_t)N_*H_];
__device__ float g_Yo [(size_t)N_*H_];
// 9 BN stat slots: 0=bn1,1=bn2, 2+2l=bnA(l), 3+2l=bnB(l), 8=bno
__device__ float g_sumA[9*256], g_sumsqA[9*256];
// fp16 operands
__device__ __half w1s_hi[64*128];
__device__ __half w2s_hi[128*256];
__device__ __half pw1s_hi[3*256*128];
__device__ __half pw2s_hi[3*128*128];
__device__ __half wo1s_hi[128*128];
__device__ __half g_evhi[(size_t)B_*V_*K_];
__device__ __half g_eihi[(size_t)B_*V_*K_];
__device__ __half g_hhi [(size_t)N_*H_];
__device__ __half g_Thi [(size_t)B_*K_*H_];

// ---------------- helpers ----------------
__device__ __forceinline__ float siluf(float x){ return x * (1.f/(1.f+__expf(-x))); }
__device__ __forceinline__ float softplusf(float x){ return x > 20.f ? x : log1pf(__expf(x)); }
__device__ __forceinline__ void red_add_v4(float* a, float x, float y, float z, float w){
    asm volatile("red.global.add.v4.f32 [%0], {%1,%2,%3,%4};"
                 :: "l"(a), "f"(x), "f"(y), "f"(z), "f"(w) : "memory");
}
__device__ __forceinline__ uint32_t smem_u32(const void* p){
    uint32_t a;
    asm("{ .reg .u64 t; cvta.to.shared.u64 t, %1; cvt.u32.u64 %0, t; }" : "=r"(a) : "l"(p));
    return a;
}
__device__ __forceinline__ void cpasync16(uint32_t s, const void* g){
    asm volatile("cp.async.ca.shared.global [%0], [%1], 16;" :: "r"(s), "l"(g));
}
#define CP_COMMIT() asm volatile("cp.async.commit_group;")
#define CP_WAIT0()  asm volatile("cp.async.wait_group 0;")

__device__ __forceinline__ void ldsm4(uint32_t* r, uint32_t addr){
    asm volatile("ldmatrix.sync.aligned.m8n8.x4.shared.b16 {%0,%1,%2,%3}, [%4];"
        : "=r"(r[0]),"=r"(r[1]),"=r"(r[2]),"=r"(r[3]) : "r"(addr));
}
__device__ __forceinline__ void ldsm4t(uint32_t* r, uint32_t addr){
    asm volatile("ldmatrix.sync.aligned.m8n8.x4.trans.shared.b16 {%0,%1,%2,%3}, [%4];"
        : "=r"(r[0]),"=r"(r[1]),"=r"(r[2]),"=r"(r[3]) : "r"(addr));
}
__device__ __forceinline__ void mma16816(float* d, const uint32_t* a, uint32_t b0, uint32_t b1){
    asm volatile("mma.sync.aligned.m16n8k16.row.col.f32.f16.f16.f32 "
        "{%0,%1,%2,%3}, {%4,%5,%6,%7}, {%8,%9}, {%0,%1,%2,%3};"
        : "+f"(d[0]),"+f"(d[1]),"+f"(d[2]),"+f"(d[3])
        : "r"(a[0]),"r"(a[1]),"r"(a[2]),"r"(a[3]), "r"(b0),"r"(b1));
}

__device__ __forceinline__ uint4 cvt8h(const float* f){
    unsigned h[4];
    #pragma unroll
    for (int p=0;p<4;p++){
        __half2 hh = __float22half2_rn(make_float2(f[2*p], f[2*p+1]));
        h[p] = *reinterpret_cast<unsigned*>(&hh);
    }
    return make_uint4(h[0],h[1],h[2],h[3]);
}
__device__ __forceinline__ void unpack8h(uint4 u, float* f){
    const unsigned v[4] = {u.x, u.y, u.z, u.w};
    #pragma unroll
    for (int p=0;p<4;p++){
        float2 a = __half22float2(*reinterpret_cast<const __half2*>(&v[p]));
        f[2*p] = a.x; f[2*p+1] = a.y;
    }
}
__device__ __forceinline__ void bn_coef(const float* sum, const float* sumsq,
                                        const float* gam, const float* bet,
                                        float Rinv, int c, float& sc, float& sh){
    const float m   = sum[c]*Rinv;
    const float var = sumsq[c]*Rinv - m*m;
    sc = gam[c] * rsqrtf(var + EPSF);
    sh = bet[c] - m*sc;
}

__global__ void zero_kernel(float* __restrict__ p, size_t n){
    size_t i = (size_t)blockIdx.x*blockDim.x + threadIdx.x;
    if (i < n) p[i] = 0.f;
}
__global__ void init_all(float* __restrict__ outp){
    const int t = threadIdx.x;
    #pragma unroll
    for (int s=0;s<9;s++){ g_sumA[s*256+t]=0.f; g_sumsqA[s*256+t]=0.f; }
    if (t < 64) outp[t] = 0.f;
}

// ---------------- prep: all weights in one kernel ----------------
__global__ void split_all_weights(const float* __restrict__ w1, const float* __restrict__ w2,
                                  const float* __restrict__ pw1, const float* __restrict__ pw2,
                                  const float* __restrict__ wo1){
    const int i = blockIdx.x*256 + threadIdx.x;
    if (i < 8192){
        int k = i >> 7, n = i & 127;
        w1s_hi[i] = __float2half_rn((k < CF_) ? w1[k*128 + n] : 0.f);
        return;
    }
    int j = i - 8192;
    if (j < 32768){ w2s_hi[j] = __float2half_rn(w2[j]); return; }
    j -= 32768;
    if (j < 98304){ pw1s_hi[j] = __float2half_rn(pw1[j]); return; }
    j -= 98304;
    if (j < 49152){ pw2s_hi[j] = __float2half_rn(pw2[j]); return; }
    j -= 49152;
    if (j < 16384) wo1s_hi[j] = __float2half_rn(wo1[j]);
}
__global__ void split_eigs_k(const float* __restrict__ eigs){
    size_t i = (size_t)blockIdx.x*256 + threadIdx.x;
    size_t b = i >> 18, rem = i & 0x3FFFF;
    const float* base = eigs + (b*(size_t)(2*V_+1) + 1)*K_;
    g_evhi[i] = __float2half_rn(base[rem]);
    g_eihi[i] = __float2half_rn(base[(size_t)V_*K_ + rem]);
}

// ---------------- hoisted activation: Xh = silu(bn1(Y1h)), fp16 ----------------
// each thread handles 8 consecutive elements (one uint4 of half2)
__global__ void __launch_bounds__(256) act_silu(
    const __half* __restrict__ Y1h, __half* __restrict__ Xh,
    const float* __restrict__ g1, const float* __restrict__ be1, float Rinv)
{
    __shared__ float sc[128], sh[128];
    const int tid = threadIdx.x;
    if (tid < 128){
        float a, b;
        bn_coef(g_sumA + 0*256, g_sumsqA + 0*256, g1, be1, Rinv, tid, a, b);
        sc[tid] = a; sh[tid] = b;
    }
    __syncthreads();
    const size_t i = ((size_t)blockIdx.x*256 + tid) * 8;
    const int c0 = (int)(i & 127);
    float av[8];
    unpack8h(*reinterpret_cast<const uint4*>(Y1h + i), av);
    #pragma unroll
    for (int j=0;j<8;j++) av[j] = siluf(av[j]*sc[c0+j] + sh[c0+j]);
    *reinterpret_cast<uint4*>(Xh + i) = cvt8h(av);
}

// ================= pipelined HMMA fp16 GEMM =================
// ASRC 0: A fp32 plain, guarded scalar loads (GEMM1, Kd=47; skips all-zero k16 steps)
// ASRC 2: A fp16 (Afh), silu(A*scale+shift), coefs computed in-block from stats
// ASRC 3: A pre-converted fp16 (cp.async)
// ASRC 5: dual concat: kc<4 -> (h @ Bhi); kc>=4 -> (evecs[batch] @ B2hi[batch])
// ASRC 6: A = sum of SPLITV fp32 partials * exp(-eig[row]*t[col])
#define APITCH 80
#define BPITCH 272
#define SMBUF  18944
template<int ASRC, bool STATS, bool OUTHALF>
__global__ void __launch_bounds__(256,2) gemm5(
    const float* __restrict__ Af, const __half* __restrict__ Afh,
    const __half* __restrict__ Ahi, const __half* __restrict__ A2hi,
    const __half* __restrict__ Bhi, const __half* __restrict__ B2hi,
    const float* __restrict__ bias, float* __restrict__ C,
    __half* __restrict__ Chi,
    int Kd, int Nd, int lda,
    size_t sAs, size_t sBs, size_t sC,
    const float* __restrict__ eigsp, const float* __restrict__ ptp, int lidx,
    const float* __restrict__ bnSum, const float* __restrict__ bnSumsq,
    const float* __restrict__ bnGam, const float* __restrict__ bnBet, float bnRinv,
    float* __restrict__ stSum, float* __restrict__ stSumsq)
{
    extern __shared__ __align__(16) uint8_t smem[];
    const uint32_t sb = smem_u32(smem);
    const int tid = threadIdx.x;
    const int lane = tid & 31, wid = tid >> 5;
    const int warpm = wid & 3, warpn = wid >> 2;
    const int brow = blockIdx.y * 128;
    const int bcol = blockIdx.x * 128;
    const int bz   = blockIdx.z;
    Ahi += sAs*bz; Bhi += sBs*bz;
    if (ASRC == 6) Af += (size_t)K_*H_*bz;
    if (C)   C   += sC*bz;
    if (Chi) Chi += sC*bz;
    const int bb = brow >> 11;
    const size_t a2base = (size_t)bb*V_*K_ + (size_t)(brow & 2047)*K_;
    const size_t b2base = (size_t)bb*K_*H_;

    const int nch = (Kd + 31) >> 5;

    const int ar = tid >> 1, akh = (tid & 1) * 16;
    const int bkr = tid >> 3, bns = (tid & 7) * 16;

    float* bnsc = reinterpret_cast<float*>(smem + 2*SMBUF + 1024);
    float* bnsh = bnsc + 128;
    if (ASRC == 2){
        if (tid < 128){
            float sc, sh;
            bn_coef(bnSum, bnSumsq, bnGam, bnBet, bnRinv, tid, sc, sh);
            bnsc[tid] = sc; bnsh[tid] = sh;
        }
        __syncthreads();
    }

    auto stageB = [&](int kc, int buf){
        const __half* shi; size_t so;
        if (ASRC == 5 && kc >= 4){
            const int gk = (kc & 3)*32 + bkr;
            shi = B2hi + b2base;
            so = (size_t)gk*128 + bns;
        } else {
            const int gk = kc*32 + bkr;
            shi = Bhi;
            so = (size_t)gk*Nd + bcol + bns;
        }
        const uint32_t dst = sb + buf*SMBUF + 10240 + bkr*BPITCH + bns*2;
        cpasync16(dst,      shi + so);
        cpasync16(dst + 16, shi + so + 8);
    };
    auto stageA_async = [&](int kc, int buf){
        const __half* hi; size_t so;
        if (ASRC == 5){
            if (kc < 4){ hi = Ahi; so = (size_t)(brow+ar)*128 + kc*32 + akh; }
            else { hi = A2hi + a2base; so = (size_t)ar*K_ + (kc & 3)*32 + akh; }
        } else {
            hi = Ahi;
            so = (size_t)(brow + ar)*lda + kc*32 + akh;
        }
        const uint32_t dst = sb + buf*SMBUF + ar*APITCH + akh*2;
        cpasync16(dst,      hi + so);
        cpasync16(dst + 16, hi + so + 8);
    };
    auto loadA_f32 = [&](int kc, float* av){
        if (ASRC == 2){
            const __half* S = Afh + (size_t)(brow+ar)*lda + kc*32 + akh;
            unpack8h(*reinterpret_cast<const uint4*>(S),     &av[0]);
            unpack8h(*reinterpret_cast<const uint4*>(S + 8), &av[8]);
        } else if (ASRC == 6){
            const float* S = Af + (size_t)(brow+ar)*lda + kc*32 + akh;
            const size_t P = (size_t)B_*K_*H_;
            #pragma unroll
            for (int q=0;q<4;q++){
                float4 v0 = *reinterpret_cast<const float4*>(S + q*4);
                float4 v1 = *reinterpret_cast<const float4*>(S + P + q*4);
                float4 v2 = *reinterpret_cast<const float4*>(S + 2*P + q*4);
                float4 v3 = *reinterpret_cast<const float4*>(S + 3*P + q*4);
                av[q*4+0] = v0.x + v1.x + v2.x + v3.x;
                av[q*4+1] = v0.y + v1.y + v2.y + v3.y;
                av[q*4+2] = v0.z + v1.z + v2.z + v3.z;
                av[q*4+3] = v0.w + v1.w + v2.w + v3.w;
            }
        } else {
            #pragma unroll
            for (int j=0;j<16;j++){
                const int k = kc*32 + akh + j;
                av[j] = (k < Kd) ? Af[(size_t)(brow+ar)*lda + k] : 0.f;
            }
        }
    };
    auto storeA_f32 = [&](int kc, int buf, float* av){
        if (ASRC == 2){
            #pragma unroll
            for (int j=0;j<16;j++){
                const int k = kc*32 + akh + j;
                av[j] = siluf(av[j]*bnsc[k] + bnsh[k]);
            }
        }
        if (ASRC == 6){
            const float eig_a = eigsp[(size_t)bz*(2*V_+1)*K_ + brow + ar];
            #pragma unroll
            for (int j=0;j<16;j++){
                const int k = kc*32 + akh + j;
                av[j] *= __expf(-eig_a * fmaxf(ptp[lidx*H_ + k], 1e-6f));
            }
        }
        uint8_t* base = smem + buf*SMBUF + ar*APITCH + akh*2;
        *reinterpret_cast<uint4*>(base)      = cvt8h(&av[0]);
        *reinterpret_cast<uint4*>(base + 16) = cvt8h(&av[8]);
    };

    constexpr bool A_F32 = (ASRC == 0) || (ASRC == 2) || (ASRC == 6);

    float d[2][8][4];
    #pragma unroll
    for (int i=0;i<2;i++)
        #pragma unroll
        for (int j=0;j<8;j++)
            #pragma unroll
            for (int q=0;q<4;q++) d[i][j][q] = 0.f;

    float av[16];
    stageB(0, 0);
    if (A_F32){ loadA_f32(0, av); storeA_f32(0, 0, av); }
    else       stageA_async(0, 0);
    CP_COMMIT();
    CP_WAIT0();
    __syncthreads();

    for (int kc = 0; kc < nch; kc++){
        const int cur = kc & 1, nxt = cur ^ 1;
        const bool more = (kc + 1 < nch);
        if (more){
            stageB(kc+1, nxt);
            if (!A_F32) stageA_async(kc+1, nxt);
            CP_COMMIT();
            if (A_F32) loadA_f32(kc+1, av);
        }
        const uint32_t aHi = sb + cur*SMBUF;
        const uint32_t bHi = aHi + 10240;
        #pragma unroll
        for (int ks=0; ks<2; ks++){
            if (ASRC != 0 || kc*32 + ks*16 < Kd){
                uint32_t ah[2][4];
                #pragma unroll
                for (int mb=0; mb<2; mb++){
                    const uint32_t ao = (uint32_t)(warpm*32 + mb*16 + (lane & 15))*APITCH
                                      + ks*32 + ((lane >> 4)*16);
                    ldsm4(ah[mb], aHi + ao);
                }
                #pragma unroll
                for (int np=0; np<4; np++){
                    const int n0 = warpn*64 + np*16;
                    const uint32_t bo = (uint32_t)(ks*16 + (lane & 15))*BPITCH
                                      + (uint32_t)n0*2 + ((lane >> 4)*16);
                    uint32_t bh[4];
                    ldsm4t(bh, bHi + bo);
                    #pragma unroll
                    for (int mb=0; mb<2; mb++){
                        mma16816(d[mb][np*2  ], ah[mb], bh[0], bh[1]);
                        mma16816(d[mb][np*2+1], ah[mb], bh[2], bh[3]);
                    }
                }
            }
        }
        if (more){
            if (A_F32) storeA_f32(kc+1, nxt, av);
            CP_WAIT0();
        }
        __syncthreads();
    }

    #pragma unroll
    for (int mb=0; mb<2; mb++){
        #pragma unroll
        for (int nb=0; nb<8; nb++){
            const int m = brow + warpm*32 + mb*16 + (lane >> 2);
            const int n = bcol + warpn*64 + nb*8 + (lane & 3)*2;
            float b0 = 0.f, b1 = 0.f;
            if (bias){ b0 = bias[n]; b1 = bias[n+1]; }
            d[mb][nb][0] += b0; d[mb][nb][1] += b1;
            d[mb][nb][2] += b0; d[mb][nb][3] += b1;
            if (OUTHALF){
                __half2 h2 = __float22half2_rn(make_float2(d[mb][nb][0], d[mb][nb][1]));
                *reinterpret_cast<__half2*>(Chi + (size_t)m*Nd + n) = h2;
                __half2 h3 = __float22half2_rn(make_float2(d[mb][nb][2], d[mb][nb][3]));
                *reinterpret_cast<__half2*>(Chi + (size_t)(m+8)*Nd + n) = h3;
            } else {
                *reinterpret_cast<float2*>(C + (size_t)m*Nd + n) =
                    make_float2(d[mb][nb][0], d[mb][nb][1]);
                *reinterpret_cast<float2*>(C + (size_t)(m+8)*Nd + n) =
                    make_float2(d[mb][nb][2], d[mb][nb][3]);
            }
        }
    }

    if (STATS){
        float* sred = reinterpret_cast<float*>(smem + 2*SMBUF);
        sred[tid] = 0.f;
        __syncthreads();
        float s[16], q[16];
        #pragma unroll
        for (int i=0;i<16;i++){ s[i]=0.f; q[i]=0.f; }
        #pragma unroll
        for (int mb=0; mb<2; mb++)
            #pragma unroll
            for (int nb=0; nb<8; nb++){
                s[nb*2+0] += d[mb][nb][0] + d[mb][nb][2];
                s[nb*2+1] += d[mb][nb][1] + d[mb][nb][3];
                q[nb*2+0] += d[mb][nb][0]*d[mb][nb][0] + d[mb][nb][2]*d[mb][nb][2];
                q[nb*2+1] += d[mb][nb][1]*d[mb][nb][1] + d[mb][nb][3]*d[mb][nb][3];
            }
        #pragma unroll
        for (int off=4; off<32; off<<=1){
            #pragma unroll
            for (int i=0;i<16;i++){
                s[i] += __shfl_xor_sync(0xFFFFFFFFu, s[i], off);
                q[i] += __shfl_xor_sync(0xFFFFFFFFu, q[i], off);
            }
        }
        if (lane < 4){
            #pragma unroll
            for (int i=0;i<16;i++){
                const int col = warpn*64 + (i>>1)*8 + (lane & 3)*2 + (i & 1);
                atomicAdd(&sred[col], s[i]);
                atomicAdd(&sred[128+col], q[i]);
            }
        }
        __syncthreads();
        if (tid < 128){
            atomicAdd(&stSum  [bcol + tid], sred[tid]);
            atomicAdd(&stSumsq[bcol + tid], sred[128 + tid]);
        }
    }
}

// ================= spectral forward =================
#define SSMBUF 17408
__global__ void __launch_bounds__(256,2) spec5(float* __restrict__ HSp)
{
    extern __shared__ __align__(16) uint8_t smem[];
    const uint32_t sb = smem_u32(smem);
    const int b   = blockIdx.z;
    const int seg = blockIdx.x;
    const __half* Ahi = g_eihi + (size_t)b*V_*K_;
    const __half* Bhi = g_hhi  + (size_t)b*V_*H_;

    const int tid = threadIdx.x;
    const int lane = tid & 31, wid = tid >> 5;
    const int warpm = wid & 3, warpn = wid >> 2;
    const int vr = tid >> 3, cs = (tid & 7) * 16;
    const int v0 = seg * (V_/SPLITV);
    const int nch = V_/SPLITV/32;

    auto stage = [&](int vc, int buf){
        const int v = v0 + vc*32 + vr;
        const size_t soA = (size_t)v*K_ + cs;
        const size_t soB = (size_t)v*H_ + cs;
        const uint32_t base = sb + buf*SSMBUF + vr*BPITCH + cs*2;
        cpasync16(base,             Ahi + soA);
        cpasync16(base + 16,        Ahi + soA + 8);
        cpasync16(base + 8704,      Bhi + soB);
        cpasync16(base + 8704 + 16, Bhi + soB + 8);
    };

    float d[2][8][4];
    #pragma unroll
    for (int i=0;i<2;i++)
        #pragma unroll
        for (int j=0;j<8;j++)
            #pragma unroll
            for (int q=0;q<4;q++) d[i][j][q] = 0.f;

    stage(0, 0);
    CP_COMMIT();
    CP_WAIT0();
    __syncthreads();

    for (int vc = 0; vc < nch; vc++){
        const int cur = vc & 1, nxt = cur ^ 1;
        const bool more = (vc + 1 < nch);
        if (more){ stage(vc+1, nxt); CP_COMMIT(); }

        const uint32_t aHi = sb + cur*SSMBUF;
        const uint32_t bHi = aHi + 8704;
        #pragma unroll
        for (int ks=0; ks<2; ks++){
            uint32_t ah[2][4];
            #pragma unroll
            for (int mb=0; mb<2; mb++){
                const uint32_t ao = (uint32_t)(ks*16 + (lane & 7) + ((lane >> 4)*8))*BPITCH
                                  + (uint32_t)(warpm*32 + mb*16)*2 + (((lane >> 3) & 1)*16);
                ldsm4t(ah[mb], aHi + ao);
            }
            #pragma unroll
            for (int np=0; np<4; np++){
                const int n0 = warpn*64 + np*16;
                const uint32_t bo = (uint32_t)(ks*16 + (lane & 15))*BPITCH
                                  + (uint32_t)n0*2 + ((lane >> 4)*16);
                uint32_t bh[4];
                ldsm4t(bh, bHi + bo);
                #pragma unroll
                for (int mb=0; mb<2; mb++){
                    mma16816(d[mb][np*2  ], ah[mb], bh[0], bh[1]);
                    mma16816(d[mb][np*2+1], ah[mb], bh[2], bh[3]);
                }
            }
        }
        if (more) CP_WAIT0();
        __syncthreads();
    }

    float* Cb = HSp + (size_t)seg*B_*K_*H_ + (size_t)b*K_*H_;
    #pragma unroll
    for (int mb=0; mb<2; mb++)
        #pragma unroll
        for (int nb=0; nb<8; nb++){
            const int m = warpm*32 + mb*16 + (lane >> 2);
            const int n = warpn*64 + nb*8 + (lane & 3)*2;
            *reinterpret_cast<float2*>(Cb + (size_t)m*H_ + n) =
                make_float2(d[mb][nb][0], d[mb][nb][1]);
            *reinterpret_cast<float2*>(Cb + (size_t)(m+8)*H_ + n) =
                make_float2(d[mb][nb][2], d[mb][nb][3]);
        }
}

// ---------------- message + scatter-add ----------------
__global__ void msg_scatter(const __half* __restrict__ Y2h, const int* __restrict__ vid,
                            float* __restrict__ Hout,
                            const float* __restrict__ g2, const float* __restrict__ be2,
                            float Rinv)
{
    __shared__ float sc[256], sh[256];
    const int tid = threadIdx.x;
    for (int c = tid; c < 256; c += 128){
        float a, b;
        bn_coef(g_sumA + 1*256, g_sumsqA + 1*256, g2, be2, Rinv, c, a, b);
        sc[c] = a; sh[c] = b;
    }
    __syncthreads();

    const int sub = tid >> 5;
    const int c4  = (tid & 31) * 4;
    const int e0  = blockIdx.x * 32 + sub * 8;
    const float s0=sc[c4], s1=sc[c4+1], s2=sc[c4+2], s3=sc[c4+3];
    const float t0=sh[c4], t1=sh[c4+1], t2=sh[c4+2], t3=sh[c4+3];
    const float u0=sc[128+c4], u1=sc[129+c4], u2=sc[130+c4], u3=sc[131+c4];
    const float w0=sh[128+c4], w1=sh[129+c4], w2=sh[130+c4], w3=sh[131+c4];
    #pragma unroll
    for (int i=0;i<8;i++){
        const int e = e0 + i;
        uint2 fu = *reinterpret_cast<const uint2*>(Y2h + (size_t)e*256 + c4);
        uint2 cu = *reinterpret_cast<const uint2*>(Y2h + (size_t)e*256 + 128 + c4);
        float2 fa = __half22float2(*reinterpret_cast<const __half2*>(&fu.x));
        float2 fb = __half22float2(*reinterpret_cast<const __half2*>(&fu.y));
        float2 ca = __half22float2(*reinterpret_cast<const __half2*>(&cu.x));
        float2 cb = __half22float2(*reinterpret_cast<const __half2*>(&cu.y));
        float m0 = (1.f/(1.f+__expf(-(fa.x*s0+t0)))) * softplusf(ca.x*u0+w0);
        float m1 = (1.f/(1.f+__expf(-(fa.y*s1+t1)))) * softplusf(ca.y*u1+w1);
        float m2 = (1.f/(1.f+__expf(-(fb.x*s2+t2)))) * softplusf(cb.x*u2+w2);
        float m3 = (1.f/(1.f+__expf(-(fb.y*s3+t3)))) * softplusf(cb.y*u3+w3);
        const int v = vid[e];
        red_add_v4(Hout + (size_t)v*128 + c4, m0, m1, m2, m3);
    }
}

// h += bn(Ybh); also emit fp16 H
__global__ void h_update_split(float* __restrict__ H, const __half* __restrict__ Ybh,
                               const float* __restrict__ sum, const float* __restrict__ sumsq,
                               const float* __restrict__ g, const float* __restrict__ be,
                               float Rinv)
{
    __shared__ float sc[128], sh[128];
    const int tid = threadIdx.x;
    if (tid < 128){
        float a, b;
        bn_coef(sum, sumsq, g, be, Rinv, tid, a, b);
        sc[tid] = a; sh[tid] = b;
    }
    __syncthreads();
    const size_t i = (size_t)blockIdx.x*256 + tid;
    const int c = (int)(i & 127);
    const float v = H[i] + __half2float(Ybh[i])*sc[c] + sh[c];
    H[i] = v;
    g_hhi[i] = __float2half_rn(v);
}
__global__ void split_H(const float* __restrict__ H){
    const size_t i = (size_t)blockIdx.x*256 + threadIdx.x;
    g_hhi[i] = __float2half_rn(H[i]);
}

// out[b] += mean_v( silu(bn(Yo)) . wo2 + bo2 )
__global__ void out_reduce(const float* __restrict__ Yo, const float* __restrict__ wo2,
                           const float* __restrict__ bo2, float* __restrict__ out,
                           const float* __restrict__ go, const float* __restrict__ beo,
                           float Rinv)
{
    __shared__ float sc[128], sh[128];
    const int tid = threadIdx.x;
    if (tid < 128){
        float a, b;
        bn_coef(g_sumA + 8*256, g_sumsqA + 8*256, go, beo, Rinv, tid, a, b);
        sc[tid] = a; sh[tid] = b;
    }
    __syncthreads();
    const int warp = tid >> 5, lane = tid & 31;
    const long n = (long)blockIdx.x*8 + warp;
    float s = 0.f;
    #pragma unroll
    for (int j=0;j<4;j++){
        const int h = lane + j*32;
        float x = Yo[(size_t)n*128 + h]*sc[h] + sh[h];
        x = siluf(x);
        s += x * wo2[h];
    }
    #pragma unroll
    for (int o=16;o>0;o>>=1) s += __shfl_xor_sync(0xFFFFFFFFu, s, o);
    if (lane == 0){
        const int b = (int)(n >> 11);
        atomicAdd(&out[b], (s + bo2[0]) * (1.f/(float)V_));
    }
}

// ---------------- launcher ----------------
extern "C" void kernel_launch(void* const* d_in, const int* in_sizes, int n_in,
                              void* d_out, int out_size)
{
    const float* chem = (const float*)d_in[0];
    const int*   vid  = (const int*  )d_in[1];
    const float* eigs = (const float*)d_in[2];
    const float* w1   = (const float*)d_in[3];
    const float* b1   = (const float*)d_in[4];
    const float* g1   = (const float*)d_in[5];
    const float* be1  = (const float*)d_in[6];
    const float* w2   = (const float*)d_in[7];
    const float* b2   = (const float*)d_in[8];
    const float* g2   = (const float*)d_in[9];
    const float* be2  = (const float*)d_in[10];
    const float* ptim = (const float*)d_in[11];
    const float* pw1  = (const float*)d_in[12];
    const float* pb1  = (const float*)d_in[13];
    const float* pg1  = (const float*)d_in[14];
    const float* pbe1 = (const float*)d_in[15];
    const float* pw2  = (const float*)d_in[16];
    const float* pb2  = (const float*)d_in[17];
    const float* pg2  = (const float*)d_in[18];
    const float* pbe2 = (const float*)d_in[19];
    const float* wo1  = (const float*)d_in[20];
    const float* bo1  = (const float*)d_in[21];
    const float* go1  = (const float*)d_in[22];
    const float* beo1 = (const float*)d_in[23];
    const float* wo2  = (const float*)d_in[24];
    const float* bo2  = (const float*)d_in[25];
    float* outp = (float*)d_out;

    void* p;
    float *pH,*pHSp,*pYo,*pSum,*pSumsq;
    __half *pY1h,*pXh,*pY2h,*pYah,*pYbh;
    __half *pw1hi,*pw2hi,*ppw1hi,*ppw2hi,*pwo1hi;
    __half *pevhi,*phhi,*pThi;
    cudaGetSymbolAddress(&p, g_Y1h); pY1h=(__half*)p;
    cudaGetSymbolAddress(&p, g_Xh);  pXh =(__half*)p;
    cudaGetSymbolAddress(&p, g_Y2h); pY2h=(__half*)p;
    cudaGetSymbolAddress(&p, g_H );  pH  =(float*)p;
    cudaGetSymbolAddress(&p, g_HSp); pHSp=(float*)p;
    cudaGetSymbolAddress(&p, g_Yah); pYah=(__half*)p;
    cudaGetSymbolAddress(&p, g_Ybh); pYbh=(__half*)p;
    cudaGetSymbolAddress(&p, g_Yo);  pYo =(float*)p;
    cudaGetSymbolAddress(&p, g_sumA);   pSum  =(float*)p;
    cudaGetSymbolAddress(&p, g_sumsqA); pSumsq=(float*)p;
    cudaGetSymbolAddress(&p, w1s_hi); pw1hi=(__half*)p;
    cudaGetSymbolAddress(&p, w2s_hi); pw2hi=(__half*)p;
    cudaGetSymbolAddress(&p, pw1s_hi); ppw1hi=(__half*)p;
    cudaGetSymbolAddress(&p, pw2s_hi); ppw2hi=(__half*)p;
    cudaGetSymbolAddress(&p, wo1s_hi); pwo1hi=(__half*)p;
    cudaGetSymbolAddress(&p, g_evhi); pevhi=(__half*)p;
    cudaGetSymbolAddress(&p, g_hhi ); phhi=(__half*)p;
    cudaGetSymbolAddress(&p, g_Thi ); pThi=(__half*)p;

    const int GSM = 2*SMBUF + 2048;   // 39936
    const int SSM = 2*SSMBUF;
    cudaFuncSetAttribute(gemm5<0,true ,true >, cudaFuncAttributeMaxDynamicSharedMemorySize, GSM);
    cudaFuncSetAttribute(gemm5<2,true ,true >, cudaFuncAttributeMaxDynamicSharedMemorySize, GSM);
    cudaFuncSetAttribute(gemm5<3,true ,true >, cudaFuncAttributeMaxDynamicSharedMemorySize, GSM);
    cudaFuncSetAttribute(gemm5<6,false,true >, cudaFuncAttributeMaxDynamicSharedMemorySize, GSM);
    cudaFuncSetAttribute(gemm5<5,true ,true >, cudaFuncAttributeMaxDynamicSharedMemorySize, GSM);
    cudaFuncSetAttribute(gemm5<3,true ,false>, cudaFuncAttributeMaxDynamicSharedMemorySize, GSM);
    cudaFuncSetAttribute(spec5, cudaFuncAttributeMaxDynamicSharedMemorySize, SSM);

    const float RinvE = 1.f/(float)E_;
    const float RinvN = 1.f/(float)N_;

    // launch 1: all weights
    split_all_weights<<<(8192+32768+98304+49152+16384)/256, 256>>>(w1, w2, pw1, pw2, wo1);
    // launch 2: stats + out init
    init_all<<<1, 256>>>(outp);
    // launch 3: chem MLP stage 1 -> stats slot 0
    gemm5<0,true,true><<<dim3(1, E_/128, 1), 256, GSM>>>(
        chem, nullptr, nullptr, nullptr, pw1hi, nullptr,
        b1, nullptr, pY1h, CF_, 128, CF_, 0, 0, 0, nullptr, nullptr, 0,
        nullptr, nullptr, nullptr, nullptr, 0.f,
        pSum + 0*256, pSumsq + 0*256);
    // launch 4 (profiled next round): hoisted activation
    act_silu<<<(unsigned)(((size_t)E_*H_)/(256*8)), 256>>>(pY1h, pXh, g1, be1, RinvE);
    // launch 5: stage 2, pure cp.async A path -> slot 1
    gemm5<3,true,true><<<dim3(2, E_/128, 1), 256, GSM>>>(
        nullptr, nullptr, pXh, nullptr, pw2hi, nullptr,
        b2, nullptr, pY2h, 128, 256, 128, 0, 0, 0, nullptr, nullptr, 0,
        nullptr, nullptr, nullptr, nullptr, 0.f,
        pSum + 1*256, pSumsq + 1*256);

    // remaining prep (needed only by spec/zMLP1)
    split_eigs_k<<<(unsigned)(((size_t)B_*V_*K_)/256), 256>>>(eigs);

    // ---- message + segment_sum (consume slot 1) ----
    zero_kernel<<<(unsigned)(((size_t)N_*H_)/256), 256>>>(pH, (size_t)N_*H_);
    msg_scatter<<<E_/32, 128>>>(pY2h, vid, pH, g2, be2, RinvE);
    split_H<<<(unsigned)(((size_t)N_*H_)/256), 256>>>(pH);

    // ---- propagation layers ----
    for (int l = 0; l < L_; l++){
        spec5<<<dim3(SPLITV, 1, B_), 256, SSM>>>(pHSp);
        gemm5<6,false,true><<<dim3(1, 1, B_), 256, GSM>>>(
            pHSp, nullptr, nullptr, nullptr,
            ppw1hi + (size_t)l*256*128 + 128*128, nullptr,
            nullptr, nullptr, pThi,
            128, 128, 128, 0, 0, (size_t)K_*H_, eigs, ptim, l,
            nullptr, nullptr, nullptr, nullptr, 0.f, nullptr, nullptr);
        gemm5<5,true,true><<<dim3(1, N_/128, 1), 256, GSM>>>(
            nullptr, nullptr, phhi, pevhi,
            ppw1hi + (size_t)l*256*128, pThi,
            pb1 + l*H_, nullptr, pYah, 256, 128, 128, 0, 0, 0, nullptr, nullptr, 0,
            nullptr, nullptr, nullptr, nullptr, 0.f,
            pSum + (2+2*l)*256, pSumsq + (2+2*l)*256);
        gemm5<2,true,true><<<dim3(1, N_/128, 1), 256, GSM>>>(
            nullptr, pYah, nullptr, nullptr,
            ppw2hi + (size_t)l*128*128, nullptr,
            pb2 + l*H_, nullptr, pYbh, 128, 128, 128, 0, 0, 0, nullptr, nullptr, 0,
            pSum + (2+2*l)*256, pSumsq + (2+2*l)*256, pg1 + l*H_, pbe1 + l*H_, RinvN,
            pSum + (3+2*l)*256, pSumsq + (3+2*l)*256);
        h_update_split<<<(unsigned)(((size_t)N_*H_)/256), 256>>>(
            pH, pYbh, pSum + (3+2*l)*256, pSumsq + (3+2*l)*256,
            pg2 + l*H_, pbe2 + l*H_, RinvN);
    }

    // ---- output head -> stats slot 8 ----
    gemm5<3,true,false><<<dim3(1, N_/128, 1), 256, GSM>>>(
        nullptr, nullptr, phhi, nullptr, pwo1hi, nullptr,
        bo1, pYo, nullptr, 128, 128, 128, 0, 0, 0, nullptr, nullptr, 0,
        nullptr, nullptr, nullptr, nullptr, 0.f,
        pSum + 8*256, pSumsq + 8*256);
    out_reduce<<<N_/8, 256>>>(pYo, wo2, bo2, outp, go1, beo1, RinvN);
}